// round 10
// baseline (speedup 1.0000x reference)
#include <cuda_runtime.h>
#include <cuda_bf16.h>
#include <math.h>
#include <stdint.h>

// Problem constants
#define BNUM 8
#define TNUM 1024
#define CDIM 512
#define EDIM 256
#define HNUM 8
#define BT   8192
#define QKV_LD 6144
#define HE   2048

typedef __nv_bfloat16 bf16;
typedef __nv_bfloat162 bf162;

// Scratch (__device__ globals; no allocation allowed)
__device__ bf16  g_x1b[(long)BT * EDIM];
__device__ bf16  g_Wcat[(long)QKV_LD * EDIM];
__device__ bf16  g_Wub[(long)EDIM * HE];
__device__ bf16  g_qkv[(long)BT * QKV_LD];
__device__ bf16  g_P[(long)BNUM * HNUM * TNUM * TNUM];   // bf16 logits -> softmax in place
__device__ bf16  g_O[(long)BT * HE];

__device__ __forceinline__ uint32_t sptr(const void* p) {
    return (uint32_t)__cvta_generic_to_shared(p);
}
__device__ __forceinline__ void ldm_x4(uint32_t& r0, uint32_t& r1, uint32_t& r2,
                                       uint32_t& r3, uint32_t addr) {
    asm volatile("ldmatrix.sync.aligned.m8n8.x4.shared.b16 {%0,%1,%2,%3}, [%4];"
                 : "=r"(r0), "=r"(r1), "=r"(r2), "=r"(r3) : "r"(addr));
}
__device__ __forceinline__ void ldm_x4_t(uint32_t& r0, uint32_t& r1, uint32_t& r2,
                                         uint32_t& r3, uint32_t addr) {
    asm volatile("ldmatrix.sync.aligned.m8n8.x4.trans.shared.b16 {%0,%1,%2,%3}, [%4];"
                 : "=r"(r0), "=r"(r1), "=r"(r2), "=r"(r3) : "r"(addr));
}
__device__ __forceinline__ void mma16816(float* d, const uint32_t* a, const uint32_t* b) {
    asm volatile(
        "mma.sync.aligned.m16n8k16.row.col.f32.bf16.bf16.f32 "
        "{%0,%1,%2,%3}, {%4,%5,%6,%7}, {%8,%9}, {%0,%1,%2,%3};"
        : "+f"(d[0]), "+f"(d[1]), "+f"(d[2]), "+f"(d[3])
        : "r"(a[0]), "r"(a[1]), "r"(a[2]), "r"(a[3]), "r"(b[0]), "r"(b[1]));
}
__device__ __forceinline__ void cp16(uint32_t saddr, const void* gptr) {
    asm volatile("cp.async.cg.shared.global [%0], [%1], 16;" :: "r"(saddr), "l"(gptr));
}
#define CP_COMMIT() asm volatile("cp.async.commit_group;")
#define CP_WAIT(N)  asm volatile("cp.async.wait_group %0;" :: "n"(N))

// ===========================================================================
// gemm_big: 128(M) x 256(N) CTA tile, BK=64, 8 warps as 2x4 of 64x64 tiles,
// 1 CTA/SM, 4-stage cp.async. Halves LDSM bytes per MAC vs 32x64 warp tiles.
//   TRANSB=true : C = A * B^T  (B stored [N][K])
//   TRANSB=false: C = A * B    (B stored [K][N])
// bf16 output.
// ===========================================================================
#define NSTG 4

template<bool TRANSB>
__global__ void __launch_bounds__(256, 1)
gemm_big(const bf16* __restrict__ A, const bf16* __restrict__ B,
         bf16* __restrict__ C,
         int K, int lda, int ldb, int ldc,
         int Hdiv, long sAb, long sAh, long sBb, long sBh, long sCb, long sCh)
{
    constexpr int APAD = 72;        // row stride for 64-K-wide tiles (A, NT-B)
    constexpr int BPADNN = 264;     // row stride for 256-N-wide NN-B tiles
    constexpr uint32_t A_STG = 128 * APAD * 2;                         // 18432
    constexpr uint32_t B_STG = TRANSB ? 256u * APAD * 2 : 64u * BPADNN * 2;

    extern __shared__ __align__(16) bf16 dynsmem[];
    const uint32_t sA0 = sptr(dynsmem);
    const uint32_t sB0 = sA0 + NSTG * A_STG;

    const int z  = blockIdx.z;
    const int zb = z / Hdiv;
    const int zh = z % Hdiv;
    A += zb * sAb + zh * sAh;
    B += zb * sBb + zh * sBh;

    const int mBase = blockIdx.y * 128;
    const int nBase = blockIdx.x * 256;
    const int tid   = threadIdx.x;
    const int lane  = tid & 31;
    const int warp  = tid >> 5;
    const int warpM = (warp & 1) * 64;
    const int warpN = (warp >> 1) * 64;

    const int lj = lane >> 3;
    const int lr = lane & 7;
    const int aFR = (lj & 1) * 8 + lr;
    const int aFC = (lj >> 1) * 8;
    const int bNTn = lr + 8 * (lj >> 1);
    const int bNTk = 8 * (lj & 1);
    const int bNNk = lr + 8 * (lj & 1);
    const int bNNn = 8 * (lj >> 1);

    float acc[4][8][4];
    #pragma unroll
    for (int i = 0; i < 4; i++)
        #pragma unroll
        for (int j = 0; j < 8; j++)
            #pragma unroll
            for (int q = 0; q < 4; q++) acc[i][j][q] = 0.f;

    const int ntile = K >> 6;

    auto prefetch = [&](int kt, int s) {
        const uint32_t sa = sA0 + (uint32_t)s * A_STG;
        const uint32_t sb = sB0 + (uint32_t)s * B_STG;
        const int k0 = kt << 6;
        // A tile 128x64: 1024 16B chunks, 4/thread
        #pragma unroll
        for (int u = 0; u < 4; u++) {
            const int c = tid + u * 256;
            const int r = c >> 3, cc = (c & 7) * 8;
            cp16(sa + (r * APAD + cc) * 2, &A[(long)(mBase + r) * lda + k0 + cc]);
        }
        if (TRANSB) {
            // B tile 256(N) x 64(K): 2048 chunks, 8/thread
            #pragma unroll
            for (int u = 0; u < 8; u++) {
                const int c = tid + u * 256;
                const int r = c >> 3, cc = (c & 7) * 8;
                cp16(sb + (r * APAD + cc) * 2, &B[(long)(nBase + r) * ldb + k0 + cc]);
            }
        } else {
            // B tile 64(K) x 256(N): 2048 chunks, 8/thread
            #pragma unroll
            for (int u = 0; u < 8; u++) {
                const int c = tid + u * 256;
                const int r = c >> 5, cc = (c & 31) * 8;
                cp16(sb + (r * BPADNN + cc) * 2, &B[(long)(k0 + r) * ldb + nBase + cc]);
            }
        }
    };

    uint32_t aF[2][4][4];   // [buf][mt][reg]
    uint32_t bF[2][8][2];   // [buf][nt][reg]

    auto ldsm_half = [&](uint32_t sa, uint32_t sb, int kk, int buf) {
        #pragma unroll
        for (int mt = 0; mt < 4; mt++) {
            uint32_t addr = sa + ((warpM + mt * 16 + aFR) * APAD + kk + aFC) * 2;
            ldm_x4(aF[buf][mt][0], aF[buf][mt][1], aF[buf][mt][2], aF[buf][mt][3], addr);
        }
        #pragma unroll
        for (int np = 0; np < 4; np++) {
            uint32_t r0, r1, r2, r3;
            if (TRANSB) {
                uint32_t addr = sb + ((warpN + np * 16 + bNTn) * APAD + kk + bNTk) * 2;
                ldm_x4(r0, r1, r2, r3, addr);
            } else {
                uint32_t addr = sb + ((kk + bNNk) * BPADNN + warpN + np * 16 + bNNn) * 2;
                ldm_x4_t(r0, r1, r2, r3, addr);
            }
            bF[buf][np * 2][0] = r0;     bF[buf][np * 2][1] = r1;
            bF[buf][np * 2 + 1][0] = r2; bF[buf][np * 2 + 1][1] = r3;
        }
    };

    auto mma_half = [&](int buf) {
        #pragma unroll
        for (int mt = 0; mt < 4; mt++)
            #pragma unroll
            for (int nt = 0; nt < 8; nt++)
                mma16816(acc[mt][nt], aF[buf][mt], bF[buf][nt]);
    };

    prefetch(0, 0); CP_COMMIT();
    prefetch(1, 1); CP_COMMIT();
    prefetch(2, 2); CP_COMMIT();

    int s = 0;
    for (int i = 0; i < ntile; i++) {
        CP_WAIT(2);
        __syncthreads();
        {
            const int pf = i + NSTG - 1;
            int ps = s + NSTG - 1; if (ps >= NSTG) ps -= NSTG;
            if (pf < ntile) prefetch(pf, ps);
            CP_COMMIT();
        }
        const uint32_t sa = sA0 + (uint32_t)s * A_STG;
        const uint32_t sb = sB0 + (uint32_t)s * B_STG;
        s = (s + 1 == NSTG) ? 0 : s + 1;

        ldsm_half(sa, sb, 0, 0);
        ldsm_half(sa, sb, 16, 1);
        mma_half(0);
        ldsm_half(sa, sb, 32, 0);
        mma_half(1);
        ldsm_half(sa, sb, 48, 1);
        mma_half(0);
        mma_half(1);
    }

    bf16* Cp = C + zb * sCb + zh * sCh;
    const int qr = lane >> 2;
    const int qc = (lane & 3) * 2;
    #pragma unroll
    for (int mt = 0; mt < 4; mt++) {
        #pragma unroll
        for (int nt = 0; nt < 8; nt++) {
            int r0 = mBase + warpM + mt * 16 + qr;
            int r1 = r0 + 8;
            int col = nBase + warpN + nt * 8 + qc;
            float* c = acc[mt][nt];
            *reinterpret_cast<bf162*>(&Cp[(long)r0 * ldc + col]) =
                __floats2bfloat162_rn(c[0], c[1]);
            *reinterpret_cast<bf162*>(&Cp[(long)r1 * ldc + col]) =
                __floats2bfloat162_rn(c[2], c[3]);
        }
    }
}

// ===========================================================================
// Round-8 kernel (128x128, 32x64 warp tiles, 2 CTA/SM) kept for out-proj
// with the fused residual+bias epilogue (EPI2).
// ===========================================================================
#define NSTAGE 3
#define BK 64

__global__ void __launch_bounds__(256, 2)
gemm_outproj(const bf16* __restrict__ A, const bf16* __restrict__ B,
             float* __restrict__ C, int K, int lda, int ldb,
             const float* __restrict__ xin, const float* __restrict__ bu)
{
    constexpr int APAD = 72;
    constexpr uint32_t A_STG = 128 * APAD * 2;
    constexpr uint32_t B_STG = 128 * APAD * 2;

    extern __shared__ __align__(16) bf16 dynsmem[];
    const uint32_t sA0 = sptr(dynsmem);
    const uint32_t sB0 = sA0 + NSTAGE * A_STG;

    const int mBase = blockIdx.y * 128;
    const int nBase = blockIdx.x * 128;
    const int tid   = threadIdx.x;
    const int lane  = tid & 31;
    const int warp  = tid >> 5;
    const int warpM = (warp & 3) * 32;
    const int warpN = (warp >> 2) * 64;

    const int lj = lane >> 3;
    const int lr = lane & 7;
    const int aFR = (lj & 1) * 8 + lr;
    const int aFC = (lj >> 1) * 8;
    const int bNTn = lr + 8 * (lj >> 1);
    const int bNTk = 8 * (lj & 1);

    float acc[2][8][4];
    #pragma unroll
    for (int i = 0; i < 2; i++)
        #pragma unroll
        for (int j = 0; j < 8; j++)
            #pragma unroll
            for (int q = 0; q < 4; q++) acc[i][j][q] = 0.f;

    const int ntile = K / BK;

    auto prefetch = [&](int kt, int s) {
        const uint32_t sa = sA0 + (uint32_t)s * A_STG;
        const uint32_t sb = sB0 + (uint32_t)s * B_STG;
        const int k0 = kt * BK;
        #pragma unroll
        for (int u = 0; u < 4; u++) {
            const int c = tid + u * 256;
            const int r = c >> 3, cc = (c & 7) * 8;
            cp16(sa + (r * APAD + cc) * 2, &A[(long)(mBase + r) * lda + k0 + cc]);
            cp16(sb + (r * APAD + cc) * 2, &B[(long)(nBase + r) * ldb + k0 + cc]);
        }
    };

    uint32_t aF[2][2][4];
    uint32_t bF[2][8][2];

    auto ldsm_half = [&](uint32_t sa, uint32_t sb, int kk, int buf) {
        #pragma unroll
        for (int mt = 0; mt < 2; mt++) {
            uint32_t addr = sa + ((warpM + mt * 16 + aFR) * APAD + kk + aFC) * 2;
            ldm_x4(aF[buf][mt][0], aF[buf][mt][1], aF[buf][mt][2], aF[buf][mt][3], addr);
        }
        #pragma unroll
        for (int np = 0; np < 4; np++) {
            uint32_t r0, r1, r2, r3;
            uint32_t addr = sb + ((warpN + np * 16 + bNTn) * APAD + kk + bNTk) * 2;
            ldm_x4(r0, r1, r2, r3, addr);
            bF[buf][np * 2][0] = r0;     bF[buf][np * 2][1] = r1;
            bF[buf][np * 2 + 1][0] = r2; bF[buf][np * 2 + 1][1] = r3;
        }
    };

    auto mma_half = [&](int buf) {
        #pragma unroll
        for (int mt = 0; mt < 2; mt++)
            #pragma unroll
            for (int nt = 0; nt < 8; nt++)
                mma16816(acc[mt][nt], aF[buf][mt], bF[buf][nt]);
    };

    prefetch(0, 0); CP_COMMIT();
    prefetch(1, 1); CP_COMMIT();

    int s = 0;
    for (int i = 0; i < ntile; i++) {
        CP_WAIT(1);
        __syncthreads();
        {
            const int pf = i + NSTAGE - 1;
            int ps = s + NSTAGE - 1; if (ps >= NSTAGE) ps -= NSTAGE;
            if (pf < ntile) prefetch(pf, ps);
            CP_COMMIT();
        }
        const uint32_t sa = sA0 + (uint32_t)s * A_STG;
        const uint32_t sb = sB0 + (uint32_t)s * B_STG;
        s = (s + 1 == NSTAGE) ? 0 : s + 1;

        ldsm_half(sa, sb, 0, 0);
        ldsm_half(sa, sb, 16, 1);
        mma_half(0);
        ldsm_half(sa, sb, 32, 0);
        mma_half(1);
        ldsm_half(sa, sb, 48, 1);
        mma_half(0);
        mma_half(1);
    }

    const int qr = lane >> 2;
    const int qc = (lane & 3) * 2;
    #pragma unroll
    for (int mt = 0; mt < 2; mt++) {
        #pragma unroll
        for (int nt = 0; nt < 8; nt++) {
            int r0 = mBase + warpM + mt * 16 + qr;
            int r1 = r0 + 8;
            int col = nBase + warpN + nt * 8 + qc;
            float* c = acc[mt][nt];
            float b0 = bu[col], b1 = bu[col + 1];
            long o0 = (long)r0 * CDIM + EDIM + col;
            long o1 = (long)r1 * CDIM + EDIM + col;
            C[o0]     = c[0] + b0 + xin[o0];
            C[o0 + 1] = c[1] + b1 + xin[o0 + 1];
            C[o1]     = c[2] + b0 + xin[o1];
            C[o1 + 1] = c[3] + b1 + xin[o1 + 1];
        }
    }
}

// ---------------------------------------------------------------------------
// Warp-per-row softmax, in place on bf16 rows of 1024. 8 rows per CTA.
// ---------------------------------------------------------------------------
__global__ void __launch_bounds__(256)
softmax_bf16(bf16* __restrict__ P)
{
    const long row = (long)blockIdx.x * 8 + (threadIdx.x >> 5);
    const int lane = threadIdx.x & 31;
    uint4* p4 = reinterpret_cast<uint4*>(P + row * 1024);

    uint4 v[4];
    float f[32];
    #pragma unroll
    for (int c = 0; c < 4; c++) {
        v[c] = p4[c * 32 + lane];
        const bf162* h = reinterpret_cast<const bf162*>(&v[c]);
        #pragma unroll
        for (int q = 0; q < 4; q++) {
            float2 t = __bfloat1622float2(h[q]);
            f[c * 8 + q * 2]     = t.x;
            f[c * 8 + q * 2 + 1] = t.y;
        }
    }
    float m = f[0];
    #pragma unroll
    for (int i = 1; i < 32; i++) m = fmaxf(m, f[i]);
    #pragma unroll
    for (int o = 16; o; o >>= 1) m = fmaxf(m, __shfl_xor_sync(~0u, m, o));

    float s = 0.f;
    #pragma unroll
    for (int i = 0; i < 32; i++) { f[i] = __expf(f[i] - m); s += f[i]; }
    #pragma unroll
    for (int o = 16; o; o >>= 1) s += __shfl_xor_sync(~0u, s, o);
    const float r = 1.f / s;

    #pragma unroll
    for (int c = 0; c < 4; c++) {
        bf162* h = reinterpret_cast<bf162*>(&v[c]);
        #pragma unroll
        for (int q = 0; q < 4; q++)
            h[q] = __floats2bfloat162_rn(f[c * 8 + q * 2] * r, f[c * 8 + q * 2 + 1] * r);
        p4[c * 32 + lane] = v[c];
    }
}

// ---------------------------------------------------------------------------
// Fused: out[:, :256] = x1 (fp32 copy) AND x1b = bf16(x1)
// ---------------------------------------------------------------------------
__global__ void __launch_bounds__(256)
prep_x1(const float* __restrict__ x, float* __restrict__ out, bf16* __restrict__ x1b)
{
    long idx = (long)blockIdx.x * 256 + threadIdx.x;   // over BT*64
    long row = idx >> 6;
    int  c4  = (int)(idx & 63) * 4;
    float4 v = *reinterpret_cast<const float4*>(&x[row * CDIM + c4]);
    *reinterpret_cast<float4*>(&out[row * CDIM + c4]) = v;
    bf162* d = reinterpret_cast<bf162*>(&x1b[row * EDIM + c4]);
    d[0] = __floats2bfloat162_rn(v.x, v.y);
    d[1] = __floats2bfloat162_rn(v.z, v.w);
}

__global__ void __launch_bounds__(256)
conv_wcat(const float* __restrict__ Wq, const float* __restrict__ Wk,
          const float* __restrict__ Wv, bf16* __restrict__ dst)
{
    long idx = (long)blockIdx.x * 256 + threadIdx.x;   // over 6144*64
    long row = idx >> 6;
    int  c4  = (int)(idx & 63) * 4;
    const float* src; float s;
    if (row < 2048)      { src = Wq + row * EDIM;          s = 0.25f; }
    else if (row < 4096) { src = Wk + (row - 2048) * EDIM; s = 0.25f; }
    else                 { src = Wv + (row - 4096) * EDIM; s = 1.0f;  }
    float4 v = *reinterpret_cast<const float4*>(&src[c4]);
    bf162* d = reinterpret_cast<bf162*>(&dst[row * EDIM + c4]);
    d[0] = __floats2bfloat162_rn(v.x * s, v.y * s);
    d[1] = __floats2bfloat162_rn(v.z * s, v.w * s);
}

__global__ void __launch_bounds__(256)
conv_wu(const float* __restrict__ Wu, bf16* __restrict__ dst)
{
    long idx = (long)blockIdx.x * 256 + threadIdx.x;   // over 256*512
    long row = idx >> 9;
    int  c4  = (int)(idx & 511) * 4;
    float4 v = *reinterpret_cast<const float4*>(&Wu[row * HE + c4]);
    bf162* d = reinterpret_cast<bf162*>(&dst[row * HE + c4]);
    d[0] = __floats2bfloat162_rn(v.x, v.y);
    d[1] = __floats2bfloat162_rn(v.z, v.w);
}

// ---------------------------------------------------------------------------
extern "C" void kernel_launch(void* const* d_in, const int* in_sizes, int n_in,
                              void* d_out, int out_size)
{
    const float* x  = (const float*)d_in[0];
    const float* Wq = (const float*)d_in[1];
    const float* Wk = (const float*)d_in[2];
    const float* Wv = (const float*)d_in[3];
    const float* Wu = (const float*)d_in[4];
    const float* bu = (const float*)d_in[5];
    float* out = (float*)d_out;

    bf16 *x1b, *Wcat, *Wub, *qkv, *P, *O;
    cudaGetSymbolAddress((void**)&x1b,  g_x1b);
    cudaGetSymbolAddress((void**)&Wcat, g_Wcat);
    cudaGetSymbolAddress((void**)&Wub,  g_Wub);
    cudaGetSymbolAddress((void**)&qkv,  g_qkv);
    cudaGetSymbolAddress((void**)&P,    g_P);
    cudaGetSymbolAddress((void**)&O,    g_O);

    const dim3 blk(256);
    // gemm_big smem: 4 stages
    const int smemBigNT = NSTG * (128 * 72 * 2 + 256 * 72 * 2);   // 221184
    const int smemBigNN = NSTG * (128 * 72 * 2 + 64 * 264 * 2);   // 208896
    // out-proj kernel smem: 3 stages of (A + B) @128x128
    const int smemOP = NSTAGE * (128 * 72 * 2) * 2;               // 110592

    cudaFuncSetAttribute(gemm_big<true>,  cudaFuncAttributeMaxDynamicSharedMemorySize, smemBigNT);
    cudaFuncSetAttribute(gemm_big<false>, cudaFuncAttributeMaxDynamicSharedMemorySize, smemBigNN);
    cudaFuncSetAttribute(gemm_outproj,    cudaFuncAttributeMaxDynamicSharedMemorySize, smemOP);

    // 0) prep: out[:,:256]=x1, x1b=bf16(x1); weight conversions (scale folded)
    prep_x1  <<<BT * 64 / 256, blk>>>(x, out, x1b);
    conv_wcat<<<QKV_LD * 64 / 256, blk>>>(Wq, Wk, Wv, Wcat);
    conv_wu  <<<EDIM * 512 / 256, blk>>>(Wu, Wub);

    // 1) QKV = x1b @ Wcat^T  -> bf16 [8192, 6144]
    {
        dim3 g(QKV_LD / 256, BT / 128, 1);
        gemm_big<true><<<g, blk, smemBigNT>>>(x1b, Wcat, qkv, EDIM, EDIM, EDIM, QKV_LD,
                                              1, 0, 0, 0, 0, 0, 0);
    }
    // 2) S[b,h] = Q @ K^T -> bf16 logits in g_P
    {
        dim3 g(TNUM / 256, TNUM / 128, BNUM * HNUM);
        gemm_big<true><<<g, blk, smemBigNT>>>(
            qkv, qkv + HE, P, EDIM, QKV_LD, QKV_LD, TNUM,
            HNUM,
            (long)TNUM * QKV_LD, (long)EDIM,
            (long)TNUM * QKV_LD, (long)EDIM,
            (long)HNUM * TNUM * TNUM, (long)TNUM * TNUM);
    }
    // 3) softmax in place on g_P (warp per row)
    softmax_bf16<<<BNUM * HNUM * TNUM / 8, blk>>>(P);

    // 4) O = P @ V  (NN)
    {
        dim3 g(EDIM / 256, TNUM / 128, BNUM * HNUM);
        gemm_big<false><<<g, blk, smemBigNN>>>(
            P, qkv + 2 * HE, O, TNUM, TNUM, QKV_LD, HE,
            HNUM,
            (long)HNUM * TNUM * TNUM, (long)TNUM * TNUM,
            (long)TNUM * QKV_LD, (long)EDIM,
            (long)TNUM * HE, (long)EDIM);
    }
    // 5) out[:,256:] = O @ Wub^T + bu + x2  (fused epilogue)
    {
        dim3 g(EDIM / 128, BT / 128, 1);
        gemm_outproj<<<g, blk, smemOP>>>(O, Wub, out, HE, HE, HE, x, bu);
    }
}

// round 12
// speedup vs baseline: 1.1043x; 1.1043x over previous
#include <cuda_runtime.h>
#include <cuda_bf16.h>
#include <math.h>
#include <stdint.h>

// Problem constants
#define BNUM 8
#define TNUM 1024
#define CDIM 512
#define EDIM 256
#define HNUM 8
#define BT   8192
#define QKV_LD 6144
#define HE   2048

typedef __nv_bfloat16 bf16;
typedef __nv_bfloat162 bf162;

// Scratch (__device__ globals; no allocation allowed)
__device__ bf16  g_x1b[(long)BT * EDIM];
__device__ bf16  g_Wcat[(long)QKV_LD * EDIM];
__device__ bf16  g_Wub[(long)EDIM * HE];
__device__ bf16  g_qkv[(long)BT * QKV_LD];
__device__ bf16  g_P[(long)BNUM * HNUM * TNUM * TNUM];   // bf16 logits -> softmax in place
__device__ bf16  g_O[(long)BT * HE];

__device__ __forceinline__ uint32_t sptr(const void* p) {
    return (uint32_t)__cvta_generic_to_shared(p);
}
__device__ __forceinline__ void ldm_x4(uint32_t& r0, uint32_t& r1, uint32_t& r2,
                                       uint32_t& r3, uint32_t addr) {
    asm volatile("ldmatrix.sync.aligned.m8n8.x4.shared.b16 {%0,%1,%2,%3}, [%4];"
                 : "=r"(r0), "=r"(r1), "=r"(r2), "=r"(r3) : "r"(addr));
}
__device__ __forceinline__ void ldm_x4_t(uint32_t& r0, uint32_t& r1, uint32_t& r2,
                                         uint32_t& r3, uint32_t addr) {
    asm volatile("ldmatrix.sync.aligned.m8n8.x4.trans.shared.b16 {%0,%1,%2,%3}, [%4];"
                 : "=r"(r0), "=r"(r1), "=r"(r2), "=r"(r3) : "r"(addr));
}
__device__ __forceinline__ void mma16816(float* d, const uint32_t* a, const uint32_t* b) {
    asm volatile(
        "mma.sync.aligned.m16n8k16.row.col.f32.bf16.bf16.f32 "
        "{%0,%1,%2,%3}, {%4,%5,%6,%7}, {%8,%9}, {%0,%1,%2,%3};"
        : "+f"(d[0]), "+f"(d[1]), "+f"(d[2]), "+f"(d[3])
        : "r"(a[0]), "r"(a[1]), "r"(a[2]), "r"(a[3]), "r"(b[0]), "r"(b[1]));
}
__device__ __forceinline__ void cp16(uint32_t saddr, const void* gptr) {
    asm volatile("cp.async.cg.shared.global [%0], [%1], 16;" :: "r"(saddr), "l"(gptr));
}
#define CP_COMMIT() asm volatile("cp.async.commit_group;")
#define CP_WAIT(N)  asm volatile("cp.async.wait_group %0;" :: "n"(N))

// ===========================================================================
// gemm_w64: 128x128 CTA tile, BK=64, 128 threads (4 warps as 2x2 of 64x64),
// 2 CTAs/SM, 3-stage cp.async. 64x64 warp tiles cut LDSM bytes/MAC 1.5x vs
// 32x64 while the second CTA hides barrier/CP_WAIT exposure.
//   TRANSB=true : C = A * B^T  (B stored [N][K])
//   TRANSB=false: C = A * B    (B stored [K][N])
// bf16 output, batched via blockIdx.z.
// ===========================================================================
#define NSTG 3

template<bool TRANSB>
__global__ void __launch_bounds__(128, 2)
gemm_w64(const bf16* __restrict__ A, const bf16* __restrict__ B,
         bf16* __restrict__ C,
         int K, int lda, int ldb, int ldc,
         int Hdiv, long sAb, long sAh, long sBb, long sBh, long sCb, long sCh)
{
    constexpr int APAD = 72;        // row stride for 64-K-wide tiles (A, NT-B)
    constexpr int BPADNN = 136;     // row stride for 128-N-wide NN-B tiles
    constexpr uint32_t A_STG = 128 * APAD * 2;                         // 18432
    constexpr uint32_t B_STG = TRANSB ? 128u * APAD * 2 : 64u * BPADNN * 2;

    extern __shared__ __align__(16) bf16 dynsmem[];
    const uint32_t sA0 = sptr(dynsmem);
    const uint32_t sB0 = sA0 + NSTG * A_STG;

    const int z  = blockIdx.z;
    const int zb = z / Hdiv;
    const int zh = z % Hdiv;
    A += zb * sAb + zh * sAh;
    B += zb * sBb + zh * sBh;

    const int mBase = blockIdx.y * 128;
    const int nBase = blockIdx.x * 128;
    const int tid   = threadIdx.x;
    const int lane  = tid & 31;
    const int warp  = tid >> 5;
    const int warpM = (warp & 1) * 64;
    const int warpN = (warp >> 1) * 64;

    const int lj = lane >> 3;
    const int lr = lane & 7;
    const int aFR = (lj & 1) * 8 + lr;
    const int aFC = (lj >> 1) * 8;
    const int bNTn = lr + 8 * (lj >> 1);
    const int bNTk = 8 * (lj & 1);
    const int bNNk = lr + 8 * (lj & 1);
    const int bNNn = 8 * (lj >> 1);

    float acc[4][8][4];
    #pragma unroll
    for (int i = 0; i < 4; i++)
        #pragma unroll
        for (int j = 0; j < 8; j++)
            #pragma unroll
            for (int q = 0; q < 4; q++) acc[i][j][q] = 0.f;

    const int ntile = K >> 6;

    auto prefetch = [&](int kt, int s) {
        const uint32_t sa = sA0 + (uint32_t)s * A_STG;
        const uint32_t sb = sB0 + (uint32_t)s * B_STG;
        const int k0 = kt << 6;
        // A tile 128x64: 1024 16B chunks, 8/thread
        #pragma unroll
        for (int u = 0; u < 8; u++) {
            const int c = tid + u * 128;
            const int r = c >> 3, cc = (c & 7) * 8;
            cp16(sa + (r * APAD + cc) * 2, &A[(long)(mBase + r) * lda + k0 + cc]);
        }
        if (TRANSB) {
            // B tile 128(N) x 64(K): 1024 chunks, 8/thread
            #pragma unroll
            for (int u = 0; u < 8; u++) {
                const int c = tid + u * 128;
                const int r = c >> 3, cc = (c & 7) * 8;
                cp16(sb + (r * APAD + cc) * 2, &B[(long)(nBase + r) * ldb + k0 + cc]);
            }
        } else {
            // B tile 64(K) x 128(N): 1024 chunks, 8/thread
            #pragma unroll
            for (int u = 0; u < 8; u++) {
                const int c = tid + u * 128;
                const int r = c >> 4, cc = (c & 15) * 8;
                cp16(sb + (r * BPADNN + cc) * 2, &B[(long)(k0 + r) * ldb + nBase + cc]);
            }
        }
    };

    uint32_t aF[2][4][4];   // [buf][mt][reg]
    uint32_t bF[2][8][2];   // [buf][nt][reg]

    auto ldsm_half = [&](uint32_t sa, uint32_t sb, int kk, int buf) {
        #pragma unroll
        for (int mt = 0; mt < 4; mt++) {
            uint32_t addr = sa + ((warpM + mt * 16 + aFR) * APAD + kk + aFC) * 2;
            ldm_x4(aF[buf][mt][0], aF[buf][mt][1], aF[buf][mt][2], aF[buf][mt][3], addr);
        }
        #pragma unroll
        for (int np = 0; np < 4; np++) {
            uint32_t r0, r1, r2, r3;
            if (TRANSB) {
                uint32_t addr = sb + ((warpN + np * 16 + bNTn) * APAD + kk + bNTk) * 2;
                ldm_x4(r0, r1, r2, r3, addr);
            } else {
                uint32_t addr = sb + ((kk + bNNk) * BPADNN + warpN + np * 16 + bNNn) * 2;
                ldm_x4_t(r0, r1, r2, r3, addr);
            }
            bF[buf][np * 2][0] = r0;     bF[buf][np * 2][1] = r1;
            bF[buf][np * 2 + 1][0] = r2; bF[buf][np * 2 + 1][1] = r3;
        }
    };

    auto mma_half = [&](int buf) {
        #pragma unroll
        for (int mt = 0; mt < 4; mt++)
            #pragma unroll
            for (int nt = 0; nt < 8; nt++)
                mma16816(acc[mt][nt], aF[buf][mt], bF[buf][nt]);
    };

    prefetch(0, 0); CP_COMMIT();
    prefetch(1, 1); CP_COMMIT();

    int s = 0;
    for (int i = 0; i < ntile; i++) {
        CP_WAIT(1);
        __syncthreads();
        {
            const int pf = i + NSTG - 1;
            int ps = s + NSTG - 1; if (ps >= NSTG) ps -= NSTG;
            if (pf < ntile) prefetch(pf, ps);
            CP_COMMIT();
        }
        const uint32_t sa = sA0 + (uint32_t)s * A_STG;
        const uint32_t sb = sB0 + (uint32_t)s * B_STG;
        s = (s + 1 == NSTG) ? 0 : s + 1;

        ldsm_half(sa, sb, 0, 0);
        ldsm_half(sa, sb, 16, 1);
        mma_half(0);
        ldsm_half(sa, sb, 32, 0);
        mma_half(1);
        ldsm_half(sa, sb, 48, 1);
        mma_half(0);
        mma_half(1);
    }

    bf16* Cp = C + zb * sCb + zh * sCh;
    const int qr = lane >> 2;
    const int qc = (lane & 3) * 2;
    #pragma unroll
    for (int mt = 0; mt < 4; mt++) {
        #pragma unroll
        for (int nt = 0; nt < 8; nt++) {
            int r0 = mBase + warpM + mt * 16 + qr;
            int r1 = r0 + 8;
            int col = nBase + warpN + nt * 8 + qc;
            float* c = acc[mt][nt];
            *reinterpret_cast<bf162*>(&Cp[(long)r0 * ldc + col]) =
                __floats2bfloat162_rn(c[0], c[1]);
            *reinterpret_cast<bf162*>(&Cp[(long)r1 * ldc + col]) =
                __floats2bfloat162_rn(c[2], c[3]);
        }
    }
}

// ===========================================================================
// Round-8 kernel (128x128, 32x64 warp tiles, 256 thr, 2 CTA/SM) for out-proj
// with the fused residual+bias epilogue.
// ===========================================================================
#define NSTAGE 3
#define BK 64

__global__ void __launch_bounds__(256, 2)
gemm_outproj(const bf16* __restrict__ A, const bf16* __restrict__ B,
             float* __restrict__ C, int K, int lda, int ldb,
             const float* __restrict__ xin, const float* __restrict__ bu)
{
    constexpr int APAD = 72;
    constexpr uint32_t A_STG = 128 * APAD * 2;
    constexpr uint32_t B_STG = 128 * APAD * 2;

    extern __shared__ __align__(16) bf16 dynsmem[];
    const uint32_t sA0 = sptr(dynsmem);
    const uint32_t sB0 = sA0 + NSTAGE * A_STG;

    const int mBase = blockIdx.y * 128;
    const int nBase = blockIdx.x * 128;
    const int tid   = threadIdx.x;
    const int lane  = tid & 31;
    const int warp  = tid >> 5;
    const int warpM = (warp & 3) * 32;
    const int warpN = (warp >> 2) * 64;

    const int lj = lane >> 3;
    const int lr = lane & 7;
    const int aFR = (lj & 1) * 8 + lr;
    const int aFC = (lj >> 1) * 8;
    const int bNTn = lr + 8 * (lj >> 1);
    const int bNTk = 8 * (lj & 1);

    float acc[2][8][4];
    #pragma unroll
    for (int i = 0; i < 2; i++)
        #pragma unroll
        for (int j = 0; j < 8; j++)
            #pragma unroll
            for (int q = 0; q < 4; q++) acc[i][j][q] = 0.f;

    const int ntile = K / BK;

    auto prefetch = [&](int kt, int s) {
        const uint32_t sa = sA0 + (uint32_t)s * A_STG;
        const uint32_t sb = sB0 + (uint32_t)s * B_STG;
        const int k0 = kt * BK;
        #pragma unroll
        for (int u = 0; u < 4; u++) {
            const int c = tid + u * 256;
            const int r = c >> 3, cc = (c & 7) * 8;
            cp16(sa + (r * APAD + cc) * 2, &A[(long)(mBase + r) * lda + k0 + cc]);
            cp16(sb + (r * APAD + cc) * 2, &B[(long)(nBase + r) * ldb + k0 + cc]);
        }
    };

    uint32_t aF[2][2][4];
    uint32_t bF[2][8][2];

    auto ldsm_half = [&](uint32_t sa, uint32_t sb, int kk, int buf) {
        #pragma unroll
        for (int mt = 0; mt < 2; mt++) {
            uint32_t addr = sa + ((warpM + mt * 16 + aFR) * APAD + kk + aFC) * 2;
            ldm_x4(aF[buf][mt][0], aF[buf][mt][1], aF[buf][mt][2], aF[buf][mt][3], addr);
        }
        #pragma unroll
        for (int np = 0; np < 4; np++) {
            uint32_t r0, r1, r2, r3;
            uint32_t addr = sb + ((warpN + np * 16 + bNTn) * APAD + kk + bNTk) * 2;
            ldm_x4(r0, r1, r2, r3, addr);
            bF[buf][np * 2][0] = r0;     bF[buf][np * 2][1] = r1;
            bF[buf][np * 2 + 1][0] = r2; bF[buf][np * 2 + 1][1] = r3;
        }
    };

    auto mma_half = [&](int buf) {
        #pragma unroll
        for (int mt = 0; mt < 2; mt++)
            #pragma unroll
            for (int nt = 0; nt < 8; nt++)
                mma16816(acc[mt][nt], aF[buf][mt], bF[buf][nt]);
    };

    prefetch(0, 0); CP_COMMIT();
    prefetch(1, 1); CP_COMMIT();

    int s = 0;
    for (int i = 0; i < ntile; i++) {
        CP_WAIT(1);
        __syncthreads();
        {
            const int pf = i + NSTAGE - 1;
            int ps = s + NSTAGE - 1; if (ps >= NSTAGE) ps -= NSTAGE;
            if (pf < ntile) prefetch(pf, ps);
            CP_COMMIT();
        }
        const uint32_t sa = sA0 + (uint32_t)s * A_STG;
        const uint32_t sb = sB0 + (uint32_t)s * B_STG;
        s = (s + 1 == NSTAGE) ? 0 : s + 1;

        ldsm_half(sa, sb, 0, 0);
        ldsm_half(sa, sb, 16, 1);
        mma_half(0);
        ldsm_half(sa, sb, 32, 0);
        mma_half(1);
        ldsm_half(sa, sb, 48, 1);
        mma_half(0);
        mma_half(1);
    }

    const int qr = lane >> 2;
    const int qc = (lane & 3) * 2;
    #pragma unroll
    for (int mt = 0; mt < 2; mt++) {
        #pragma unroll
        for (int nt = 0; nt < 8; nt++) {
            int r0 = mBase + warpM + mt * 16 + qr;
            int r1 = r0 + 8;
            int col = nBase + warpN + nt * 8 + qc;
            float* c = acc[mt][nt];
            float b0 = bu[col], b1 = bu[col + 1];
            long o0 = (long)r0 * CDIM + EDIM + col;
            long o1 = (long)r1 * CDIM + EDIM + col;
            C[o0]     = c[0] + b0 + xin[o0];
            C[o0 + 1] = c[1] + b1 + xin[o0 + 1];
            C[o1]     = c[2] + b0 + xin[o1];
            C[o1 + 1] = c[3] + b1 + xin[o1 + 1];
        }
    }
}

// ---------------------------------------------------------------------------
// Warp-per-row softmax, in place on bf16 rows of 1024. 8 rows per CTA.
// ---------------------------------------------------------------------------
__global__ void __launch_bounds__(256)
softmax_bf16(bf16* __restrict__ P)
{
    const long row = (long)blockIdx.x * 8 + (threadIdx.x >> 5);
    const int lane = threadIdx.x & 31;
    uint4* p4 = reinterpret_cast<uint4*>(P + row * 1024);

    uint4 v[4];
    float f[32];
    #pragma unroll
    for (int c = 0; c < 4; c++) {
        v[c] = p4[c * 32 + lane];
        const bf162* h = reinterpret_cast<const bf162*>(&v[c]);
        #pragma unroll
        for (int q = 0; q < 4; q++) {
            float2 t = __bfloat1622float2(h[q]);
            f[c * 8 + q * 2]     = t.x;
            f[c * 8 + q * 2 + 1] = t.y;
        }
    }
    float m = f[0];
    #pragma unroll
    for (int i = 1; i < 32; i++) m = fmaxf(m, f[i]);
    #pragma unroll
    for (int o = 16; o; o >>= 1) m = fmaxf(m, __shfl_xor_sync(~0u, m, o));

    float s = 0.f;
    #pragma unroll
    for (int i = 0; i < 32; i++) { f[i] = __expf(f[i] - m); s += f[i]; }
    #pragma unroll
    for (int o = 16; o; o >>= 1) s += __shfl_xor_sync(~0u, s, o);
    const float r = 1.f / s;

    #pragma unroll
    for (int c = 0; c < 4; c++) {
        bf162* h = reinterpret_cast<bf162*>(&v[c]);
        #pragma unroll
        for (int q = 0; q < 4; q++)
            h[q] = __floats2bfloat162_rn(f[c * 8 + q * 2] * r, f[c * 8 + q * 2 + 1] * r);
        p4[c * 32 + lane] = v[c];
    }
}

// ---------------------------------------------------------------------------
// Fused: out[:, :256] = x1 (fp32 copy) AND x1b = bf16(x1)
// ---------------------------------------------------------------------------
__global__ void __launch_bounds__(256)
prep_x1(const float* __restrict__ x, float* __restrict__ out, bf16* __restrict__ x1b)
{
    long idx = (long)blockIdx.x * 256 + threadIdx.x;   // over BT*64
    long row = idx >> 6;
    int  c4  = (int)(idx & 63) * 4;
    float4 v = *reinterpret_cast<const float4*>(&x[row * CDIM + c4]);
    *reinterpret_cast<float4*>(&out[row * CDIM + c4]) = v;
    bf162* d = reinterpret_cast<bf162*>(&x1b[row * EDIM + c4]);
    d[0] = __floats2bfloat162_rn(v.x, v.y);
    d[1] = __floats2bfloat162_rn(v.z, v.w);
}

__global__ void __launch_bounds__(256)
conv_wcat(const float* __restrict__ Wq, const float* __restrict__ Wk,
          const float* __restrict__ Wv, bf16* __restrict__ dst)
{
    long idx = (long)blockIdx.x * 256 + threadIdx.x;   // over 6144*64
    long row = idx >> 6;
    int  c4  = (int)(idx & 63) * 4;
    const float* src; float s;
    if (row < 2048)      { src = Wq + row * EDIM;          s = 0.25f; }
    else if (row < 4096) { src = Wk + (row - 2048) * EDIM; s = 0.25f; }
    else                 { src = Wv + (row - 4096) * EDIM; s = 1.0f;  }
    float4 v = *reinterpret_cast<const float4*>(&src[c4]);
    bf162* d = reinterpret_cast<bf162*>(&dst[row * EDIM + c4]);
    d[0] = __floats2bfloat162_rn(v.x * s, v.y * s);
    d[1] = __floats2bfloat162_rn(v.z * s, v.w * s);
}

__global__ void __launch_bounds__(256)
conv_wu(const float* __restrict__ Wu, bf16* __restrict__ dst)
{
    long idx = (long)blockIdx.x * 256 + threadIdx.x;   // over 256*512
    long row = idx >> 9;
    int  c4  = (int)(idx & 511) * 4;
    float4 v = *reinterpret_cast<const float4*>(&Wu[row * HE + c4]);
    bf162* d = reinterpret_cast<bf162*>(&dst[row * HE + c4]);
    d[0] = __floats2bfloat162_rn(v.x, v.y);
    d[1] = __floats2bfloat162_rn(v.z, v.w);
}

// ---------------------------------------------------------------------------
extern "C" void kernel_launch(void* const* d_in, const int* in_sizes, int n_in,
                              void* d_out, int out_size)
{
    const float* x  = (const float*)d_in[0];
    const float* Wq = (const float*)d_in[1];
    const float* Wk = (const float*)d_in[2];
    const float* Wv = (const float*)d_in[3];
    const float* Wu = (const float*)d_in[4];
    const float* bu = (const float*)d_in[5];
    float* out = (float*)d_out;

    bf16 *x1b, *Wcat, *Wub, *qkv, *P, *O;
    cudaGetSymbolAddress((void**)&x1b,  g_x1b);
    cudaGetSymbolAddress((void**)&Wcat, g_Wcat);
    cudaGetSymbolAddress((void**)&Wub,  g_Wub);
    cudaGetSymbolAddress((void**)&qkv,  g_qkv);
    cudaGetSymbolAddress((void**)&P,    g_P);
    cudaGetSymbolAddress((void**)&O,    g_O);

    // gemm_w64 smem: 3 stages
    const int smemNT = NSTG * (128 * 72 * 2) * 2;                 // 110592
    const int smemNN = NSTG * (128 * 72 * 2 + 64 * 136 * 2);      // 107520
    const int smemOP = NSTAGE * (128 * 72 * 2) * 2;               // 110592

    cudaFuncSetAttribute(gemm_w64<true>,  cudaFuncAttributeMaxDynamicSharedMemorySize, smemNT);
    cudaFuncSetAttribute(gemm_w64<false>, cudaFuncAttributeMaxDynamicSharedMemorySize, smemNN);
    cudaFuncSetAttribute(gemm_outproj,    cudaFuncAttributeMaxDynamicSharedMemorySize, smemOP);

    // 0) prep: out[:,:256]=x1, x1b=bf16(x1); weight conversions (scale folded)
    prep_x1  <<<BT * 64 / 256, 256>>>(x, out, x1b);
    conv_wcat<<<QKV_LD * 64 / 256, 256>>>(Wq, Wk, Wv, Wcat);
    conv_wu  <<<EDIM * 512 / 256, 256>>>(Wu, Wub);

    // 1) QKV = x1b @ Wcat^T  -> bf16 [8192, 6144]
    {
        dim3 g(QKV_LD / 128, BT / 128, 1);
        gemm_w64<true><<<g, 128, smemNT>>>(x1b, Wcat, qkv, EDIM, EDIM, EDIM, QKV_LD,
                                           1, 0, 0, 0, 0, 0, 0);
    }
    // 2) S[b,h] = Q @ K^T -> bf16 logits in g_P
    {
        dim3 g(TNUM / 128, TNUM / 128, BNUM * HNUM);
        gemm_w64<true><<<g, 128, smemNT>>>(
            qkv, qkv + HE, P, EDIM, QKV_LD, QKV_LD, TNUM,
            HNUM,
            (long)TNUM * QKV_LD, (long)EDIM,
            (long)TNUM * QKV_LD, (long)EDIM,
            (long)HNUM * TNUM * TNUM, (long)TNUM * TNUM);
    }
    // 3) softmax in place on g_P (warp per row)
    softmax_bf16<<<BNUM * HNUM * TNUM / 8, 256>>>(P);

    // 4) O = P @ V  (NN)
    {
        dim3 g(EDIM / 128, TNUM / 128, BNUM * HNUM);
        gemm_w64<false><<<g, 128, smemNN>>>(
            P, qkv + 2 * HE, O, TNUM, TNUM, QKV_LD, HE,
            HNUM,
            (long)HNUM * TNUM * TNUM, (long)TNUM * TNUM,
            (long)TNUM * QKV_LD, (long)EDIM,
            (long)TNUM * HE, (long)EDIM);
    }
    // 5) out[:,256:] = O @ Wub^T + bu + x2  (fused epilogue)
    {
        dim3 g(EDIM / 128, BT / 128, 1);
        gemm_outproj<<<g, 256, smemOP>>>(O, Wub, out, HE, HE, HE, x, bu);
    }
}

// round 15
// speedup vs baseline: 1.1429x; 1.0349x over previous
#include <cuda_runtime.h>
#include <cuda_bf16.h>
#include <math.h>
#include <stdint.h>

// Problem constants
#define BNUM 8
#define TNUM 1024
#define CDIM 512
#define EDIM 256
#define HNUM 8
#define BT   8192
#define QKV_LD 6144
#define HE   2048

typedef __nv_bfloat16 bf16;
typedef __nv_bfloat162 bf162;

// Scratch (__device__ globals; no allocation allowed)
__device__ bf16  g_x1b[(long)BT * EDIM];
__device__ bf16  g_Wcat[(long)QKV_LD * EDIM];
__device__ bf16  g_Wub[(long)EDIM * HE];
__device__ bf16  g_qkv[(long)BT * QKV_LD];
__device__ bf16  g_P[(long)BNUM * HNUM * TNUM * TNUM];   // bf16 logits -> softmax in place
__device__ bf16  g_O[(long)BT * HE];

__device__ __forceinline__ uint32_t sptr(const void* p) {
    return (uint32_t)__cvta_generic_to_shared(p);
}
__device__ __forceinline__ void ldm_x4(uint32_t& r0, uint32_t& r1, uint32_t& r2,
                                       uint32_t& r3, uint32_t addr) {
    asm volatile("ldmatrix.sync.aligned.m8n8.x4.shared.b16 {%0,%1,%2,%3}, [%4];"
                 : "=r"(r0), "=r"(r1), "=r"(r2), "=r"(r3) : "r"(addr));
}
__device__ __forceinline__ void ldm_x4_t(uint32_t& r0, uint32_t& r1, uint32_t& r2,
                                         uint32_t& r3, uint32_t addr) {
    asm volatile("ldmatrix.sync.aligned.m8n8.x4.trans.shared.b16 {%0,%1,%2,%3}, [%4];"
                 : "=r"(r0), "=r"(r1), "=r"(r2), "=r"(r3) : "r"(addr));
}
__device__ __forceinline__ void mma16816(float* d, const uint32_t* a, const uint32_t* b) {
    asm volatile(
        "mma.sync.aligned.m16n8k16.row.col.f32.bf16.bf16.f32 "
        "{%0,%1,%2,%3}, {%4,%5,%6,%7}, {%8,%9}, {%0,%1,%2,%3};"
        : "+f"(d[0]), "+f"(d[1]), "+f"(d[2]), "+f"(d[3])
        : "r"(a[0]), "r"(a[1]), "r"(a[2]), "r"(a[3]), "r"(b[0]), "r"(b[1]));
}
__device__ __forceinline__ void cp16(uint32_t saddr, const void* gptr) {
    asm volatile("cp.async.cg.shared.global [%0], [%1], 16;" :: "r"(saddr), "l"(gptr));
}
#define CP_COMMIT() asm volatile("cp.async.commit_group;")
#define CP_WAIT(N)  asm volatile("cp.async.wait_group %0;" :: "n"(N))

// ---------------------------------------------------------------------------
// bf16 tensor-core GEMM, 128x128 tile, BK=64, cp.async 3-stage pipeline,
// 256 threads (8 warps, 32x64 warp tiles), 2 CTAs/SM.  Round-8 champion
// mainloop, byte-identical ordering: CP_WAIT(1) -> __syncthreads -> prefetch.
//   TRANSB=true : C = A * B^T  (B stored [N][K])
//   TRANSB=false: C = A * B    (B stored [K][N])
// EPI 0: bf16 out; EPI 2: fused residual+bias fp32 out into out[:,256:].
// ---------------------------------------------------------------------------
#define NSTAGE 3
#define BK 64

template<int EPI, bool TRANSB>
__global__ void __launch_bounds__(256, 2)
gemm_bf16(const bf16* __restrict__ A, const bf16* __restrict__ B,
          void* __restrict__ Cv,
          int K, int lda, int ldb, int ldc,
          int Hdiv, long sAb, long sAh, long sBb, long sBh, long sCb, long sCh,
          const float* __restrict__ xin, const float* __restrict__ bu)
{
    constexpr int APAD = 72;       // bf16 row stride for 64-wide K rows
    constexpr int BPADNN = 136;    // bf16 row stride for 128-wide NN-B rows
    constexpr uint32_t A_STG = 128 * APAD * 2;                        // 18432 B
    constexpr uint32_t B_STG = TRANSB ? 128u * APAD * 2 : 64u * BPADNN * 2;

    extern __shared__ __align__(16) bf16 dynsmem[];
    const uint32_t sA0 = sptr(dynsmem);
    const uint32_t sB0 = sA0 + NSTAGE * A_STG;

    const int z  = blockIdx.z;
    const int zb = z / Hdiv;
    const int zh = z % Hdiv;
    A += zb * sAb + zh * sAh;
    B += zb * sBb + zh * sBh;

    const int mBase = blockIdx.y * 128;
    const int nBase = blockIdx.x * 128;
    const int tid   = threadIdx.x;
    const int lane  = tid & 31;
    const int warp  = tid >> 5;
    const int warpM = (warp & 3) * 32;
    const int warpN = (warp >> 2) * 64;

    const int lj = lane >> 3;
    const int lr = lane & 7;
    const int aFR = (lj & 1) * 8 + lr;
    const int aFC = (lj >> 1) * 8;
    const int bNTn = lr + 8 * (lj >> 1);
    const int bNTk = 8 * (lj & 1);
    const int bNNk = lr + 8 * (lj & 1);
    const int bNNn = 8 * (lj >> 1);

    float acc[2][8][4];
    #pragma unroll
    for (int i = 0; i < 2; i++)
        #pragma unroll
        for (int j = 0; j < 8; j++)
            #pragma unroll
            for (int q = 0; q < 4; q++) acc[i][j][q] = 0.f;

    const int ntile = K / BK;

    auto prefetch = [&](int kt, int s) {
        const uint32_t sa = sA0 + (uint32_t)s * A_STG;
        const uint32_t sb = sB0 + (uint32_t)s * B_STG;
        const int k0 = kt * BK;
        #pragma unroll
        for (int u = 0; u < 4; u++) {
            const int c = tid + u * 256;
            const int r = c >> 3, cc = (c & 7) * 8;
            cp16(sa + (r * APAD + cc) * 2, &A[(long)(mBase + r) * lda + k0 + cc]);
        }
        if (TRANSB) {
            #pragma unroll
            for (int u = 0; u < 4; u++) {
                const int c = tid + u * 256;
                const int r = c >> 3, cc = (c & 7) * 8;
                cp16(sb + (r * APAD + cc) * 2, &B[(long)(nBase + r) * ldb + k0 + cc]);
            }
        } else {
            #pragma unroll
            for (int u = 0; u < 4; u++) {
                const int c = tid + u * 256;
                const int r = c >> 4, cc = (c & 15) * 8;
                cp16(sb + (r * BPADNN + cc) * 2, &B[(long)(k0 + r) * ldb + nBase + cc]);
            }
        }
    };

    // fragment rolling buffers (one 16-K half each)
    uint32_t aF[2][2][4];   // [buf][mt][reg]
    uint32_t bF[2][8][2];   // [buf][nt][reg]

    auto ldsm_half = [&](uint32_t sa, uint32_t sb, int kk, int buf) {
        #pragma unroll
        for (int mt = 0; mt < 2; mt++) {
            uint32_t addr = sa + ((warpM + mt * 16 + aFR) * APAD + kk + aFC) * 2;
            ldm_x4(aF[buf][mt][0], aF[buf][mt][1], aF[buf][mt][2], aF[buf][mt][3], addr);
        }
        #pragma unroll
        for (int np = 0; np < 4; np++) {
            uint32_t r0, r1, r2, r3;
            if (TRANSB) {
                uint32_t addr = sb + ((warpN + np * 16 + bNTn) * APAD + kk + bNTk) * 2;
                ldm_x4(r0, r1, r2, r3, addr);
            } else {
                uint32_t addr = sb + ((kk + bNNk) * BPADNN + warpN + np * 16 + bNNn) * 2;
                ldm_x4_t(r0, r1, r2, r3, addr);
            }
            bF[buf][np * 2][0] = r0;     bF[buf][np * 2][1] = r1;
            bF[buf][np * 2 + 1][0] = r2; bF[buf][np * 2 + 1][1] = r3;
        }
    };

    auto mma_half = [&](int buf) {
        #pragma unroll
        for (int mt = 0; mt < 2; mt++)
            #pragma unroll
            for (int nt = 0; nt < 8; nt++)
                mma16816(acc[mt][nt], aF[buf][mt], bF[buf][nt]);
    };

    // preload NSTAGE-1 stages
    prefetch(0, 0); CP_COMMIT();
    prefetch(1, 1); CP_COMMIT();

    int s = 0;
    for (int i = 0; i < ntile; i++) {
        CP_WAIT(1);
        __syncthreads();
        {
            const int pf = i + NSTAGE - 1;
            int ps = s + NSTAGE - 1; if (ps >= NSTAGE) ps -= NSTAGE;
            if (pf < ntile) prefetch(pf, ps);
            CP_COMMIT();
        }
        const uint32_t sa = sA0 + (uint32_t)s * A_STG;
        const uint32_t sb = sB0 + (uint32_t)s * B_STG;
        s = (s + 1 == NSTAGE) ? 0 : s + 1;

        // rolling: ldsm(h+1) before mma(h)
        ldsm_half(sa, sb, 0, 0);
        ldsm_half(sa, sb, 16, 1);
        mma_half(0);
        ldsm_half(sa, sb, 32, 0);
        mma_half(1);
        ldsm_half(sa, sb, 48, 1);
        mma_half(0);
        mma_half(1);
    }

    const int qr = lane >> 2;
    const int qc = (lane & 3) * 2;
    #pragma unroll
    for (int mt = 0; mt < 2; mt++) {
        #pragma unroll
        for (int nt = 0; nt < 8; nt++) {
            int r0 = mBase + warpM + mt * 16 + qr;
            int r1 = r0 + 8;
            int col = nBase + warpN + nt * 8 + qc;
            float* c = acc[mt][nt];
            if (EPI == 0) {
                bf16* C = (bf16*)Cv + zb * sCb + zh * sCh;
                *reinterpret_cast<bf162*>(&C[(long)r0 * ldc + col]) =
                    __floats2bfloat162_rn(c[0], c[1]);
                *reinterpret_cast<bf162*>(&C[(long)r1 * ldc + col]) =
                    __floats2bfloat162_rn(c[2], c[3]);
            } else {
                float* C = (float*)Cv;
                float b0 = bu[col], b1 = bu[col + 1];
                long o0 = (long)r0 * CDIM + EDIM + col;
                long o1 = (long)r1 * CDIM + EDIM + col;
                C[o0]     = c[0] + b0 + xin[o0];
                C[o0 + 1] = c[1] + b1 + xin[o0 + 1];
                C[o1]     = c[2] + b0 + xin[o1];
                C[o1 + 1] = c[3] + b1 + xin[o1 + 1];
            }
        }
    }
}

// ---------------------------------------------------------------------------
// Warp-per-row softmax, in place on bf16 rows of 1024. 8 rows per CTA.
// ---------------------------------------------------------------------------
__global__ void __launch_bounds__(256)
softmax_bf16(bf16* __restrict__ P)
{
    const long row = (long)blockIdx.x * 8 + (threadIdx.x >> 5);
    const int lane = threadIdx.x & 31;
    uint4* p4 = reinterpret_cast<uint4*>(P + row * 1024);

    uint4 v[4];
    float f[32];
    #pragma unroll
    for (int c = 0; c < 4; c++) {
        v[c] = p4[c * 32 + lane];
        const bf162* h = reinterpret_cast<const bf162*>(&v[c]);
        #pragma unroll
        for (int q = 0; q < 4; q++) {
            float2 t = __bfloat1622float2(h[q]);
            f[c * 8 + q * 2]     = t.x;
            f[c * 8 + q * 2 + 1] = t.y;
        }
    }
    float m = f[0];
    #pragma unroll
    for (int i = 1; i < 32; i++) m = fmaxf(m, f[i]);
    #pragma unroll
    for (int o = 16; o; o >>= 1) m = fmaxf(m, __shfl_xor_sync(~0u, m, o));

    float s = 0.f;
    #pragma unroll
    for (int i = 0; i < 32; i++) { f[i] = __expf(f[i] - m); s += f[i]; }
    #pragma unroll
    for (int o = 16; o; o >>= 1) s += __shfl_xor_sync(~0u, s, o);
    const float r = 1.f / s;

    #pragma unroll
    for (int c = 0; c < 4; c++) {
        bf162* h = reinterpret_cast<bf162*>(&v[c]);
        #pragma unroll
        for (int q = 0; q < 4; q++)
            h[q] = __floats2bfloat162_rn(f[c * 8 + q * 2] * r, f[c * 8 + q * 2 + 1] * r);
        p4[c * 32 + lane] = v[c];
    }
}

// ---------------------------------------------------------------------------
// Fused: out[:, :256] = x1 (fp32 copy) AND x1b = bf16(x1)
// ---------------------------------------------------------------------------
__global__ void __launch_bounds__(256)
prep_x1(const float* __restrict__ x, float* __restrict__ out, bf16* __restrict__ x1b)
{
    long idx = (long)blockIdx.x * 256 + threadIdx.x;   // over BT*64
    long row = idx >> 6;
    int  c4  = (int)(idx & 63) * 4;
    float4 v = *reinterpret_cast<const float4*>(&x[row * CDIM + c4]);
    *reinterpret_cast<float4*>(&out[row * CDIM + c4]) = v;
    bf162* d = reinterpret_cast<bf162*>(&x1b[row * EDIM + c4]);
    d[0] = __floats2bfloat162_rn(v.x, v.y);
    d[1] = __floats2bfloat162_rn(v.z, v.w);
}

// ---------------------------------------------------------------------------
// Merged weight conversion: blocks [0,1536) do Wq|Wk|Wv -> Wcat (scale folded),
// blocks [1536,2048) do Wu -> Wub.
// ---------------------------------------------------------------------------
__global__ void __launch_bounds__(256)
conv_weights(const float* __restrict__ Wq, const float* __restrict__ Wk,
             const float* __restrict__ Wv, const float* __restrict__ Wu,
             bf16* __restrict__ Wcat, bf16* __restrict__ Wub)
{
    if (blockIdx.x < 1536) {
        long idx = (long)blockIdx.x * 256 + threadIdx.x;   // over 6144*64
        long row = idx >> 6;
        int  c4  = (int)(idx & 63) * 4;
        const float* src; float s;
        if (row < 2048)      { src = Wq + row * EDIM;          s = 0.25f; }
        else if (row < 4096) { src = Wk + (row - 2048) * EDIM; s = 0.25f; }
        else                 { src = Wv + (row - 4096) * EDIM; s = 1.0f;  }
        float4 v = *reinterpret_cast<const float4*>(&src[c4]);
        bf162* d = reinterpret_cast<bf162*>(&Wcat[row * EDIM + c4]);
        d[0] = __floats2bfloat162_rn(v.x * s, v.y * s);
        d[1] = __floats2bfloat162_rn(v.z * s, v.w * s);
    } else {
        long idx = (long)(blockIdx.x - 1536) * 256 + threadIdx.x;  // over 256*512
        long row = idx >> 9;
        int  c4  = (int)(idx & 511) * 4;
        float4 v = *reinterpret_cast<const float4*>(&Wu[row * HE + c4]);
        bf162* d = reinterpret_cast<bf162*>(&Wub[row * HE + c4]);
        d[0] = __floats2bfloat162_rn(v.x, v.y);
        d[1] = __floats2bfloat162_rn(v.z, v.w);
    }
}

// ---------------------------------------------------------------------------
extern "C" void kernel_launch(void* const* d_in, const int* in_sizes, int n_in,
                              void* d_out, int out_size)
{
    const float* x  = (const float*)d_in[0];
    const float* Wq = (const float*)d_in[1];
    const float* Wk = (const float*)d_in[2];
    const float* Wv = (const float*)d_in[3];
    const float* Wu = (const float*)d_in[4];
    const float* bu = (const float*)d_in[5];
    float* out = (float*)d_out;

    bf16 *x1b, *Wcat, *Wub, *qkv, *P, *O;
    cudaGetSymbolAddress((void**)&x1b,  g_x1b);
    cudaGetSymbolAddress((void**)&Wcat, g_Wcat);
    cudaGetSymbolAddress((void**)&Wub,  g_Wub);
    cudaGetSymbolAddress((void**)&qkv,  g_qkv);
    cudaGetSymbolAddress((void**)&P,    g_P);
    cudaGetSymbolAddress((void**)&O,    g_O);

    const dim3 blk(256);
    // dynamic smem: 3 stages of (A 18432 + B stage)
    const int smemNT = NSTAGE * (128 * 72 * 2) * 2;                 // 110592
    const int smemNN = NSTAGE * (128 * 72 * 2 + 64 * 136 * 2);      // 107520

    cudaFuncSetAttribute(gemm_bf16<0, true>,  cudaFuncAttributeMaxDynamicSharedMemorySize, smemNT);
    cudaFuncSetAttribute(gemm_bf16<2, true>,  cudaFuncAttributeMaxDynamicSharedMemorySize, smemNT);
    cudaFuncSetAttribute(gemm_bf16<0, false>, cudaFuncAttributeMaxDynamicSharedMemorySize, smemNN);

    // 0) prep: out[:,:256]=x1, x1b=bf16(x1); merged weight conversions
    prep_x1     <<<BT * 64 / 256, blk>>>(x, out, x1b);
    conv_weights<<<1536 + 512, blk>>>(Wq, Wk, Wv, Wu, Wcat, Wub);

    // 1) QKV = x1b @ Wcat^T  -> bf16 [8192, 6144]
    {
        dim3 g(QKV_LD / 128, BT / 128, 1);
        gemm_bf16<0, true><<<g, blk, smemNT>>>(x1b, Wcat, qkv, EDIM, EDIM, EDIM, QKV_LD,
                                               1, 0, 0, 0, 0, 0, 0, nullptr, nullptr);
    }
    // 2) S[b,h] = Q @ K^T -> bf16 logits in g_P
    {
        dim3 g(TNUM / 128, TNUM / 128, BNUM * HNUM);
        gemm_bf16<0, true><<<g, blk, smemNT>>>(
            qkv, qkv + HE, P, EDIM, QKV_LD, QKV_LD, TNUM,
            HNUM,
            (long)TNUM * QKV_LD, (long)EDIM,
            (long)TNUM * QKV_LD, (long)EDIM,
            (long)HNUM * TNUM * TNUM, (long)TNUM * TNUM,
            nullptr, nullptr);
    }
    // 3) softmax in place on g_P (warp per row)
    softmax_bf16<<<BNUM * HNUM * TNUM / 8, blk>>>(P);

    // 4) O = P @ V  (NN)
    {
        dim3 g(EDIM / 128, TNUM / 128, BNUM * HNUM);
        gemm_bf16<0, false><<<g, blk, smemNN>>>(
            P, qkv + 2 * HE, O, TNUM, TNUM, QKV_LD, HE,
            HNUM,
            (long)HNUM * TNUM * TNUM, (long)TNUM * TNUM,
            (long)TNUM * QKV_LD, (long)EDIM,
            (long)TNUM * HE, (long)EDIM,
            nullptr, nullptr);
    }
    // 5) out[:,256:] = O @ Wub^T + bu + x2  (fused epilogue)
    {
        dim3 g(EDIM / 128, BT / 128, 1);
        gemm_bf16<2, true><<<g, blk, smemNT>>>(O, Wub, out, HE, HE, HE, CDIM,
                                               1, 0, 0, 0, 0, 0, 0, x, bu);
    }
}